// round 6
// baseline (speedup 1.0000x reference)
#include <cuda_runtime.h>

// ---------------- problem constants ----------------
#define Bq   8
#define Tq   12
#define Nq   883
#define Dq   128
#define Hq   8
#define Cq   16
#define Eq   7000
#define FFq  2048
#define BTq  (Bq*Tq)            // 96
#define TNq  (BTq*Nq)           // 84768
#define EEq  (BTq*Eq)           // 672000
#define ETOT (EEq+TNq)          // 756768
#define NEG  0.2f

#define NSLICE 8
#define SLQ    (TNq / NSLICE)   // 10596 (exact: 84768 = 8*10596)

// ---------------- scratch (device globals; no allocations allowed) ----------------
__device__ float g_xl[(size_t)TNq*Dq];
__device__ float g_xr[(size_t)TNq*Dq];
__device__ float g_h [(size_t)TNq*Dq];
__device__ float g_hidden[(size_t)SLQ*FFq];   // ~87 MB, reused per M-slice
__device__ float g_tmp2[(size_t)TNq*Dq];
__device__ int   g_count[TNq];
__device__ int   g_rowptr[TNq+1];
__device__ int   g_cursor[TNq];
__device__ int   g_esrc[ETOT];
__device__ int   g_is64;

// buffer IDs for template dispatch (device-side pointer resolution)
#define BUF_EXT    0
#define BUF_XL     1
#define BUF_XR     2
#define BUF_H      3
#define BUF_HIDDEN 4
#define BUF_TMP2   5

template<int ID>
__device__ __forceinline__ float* buf_ptr(const float* ext) {
    if (ID == BUF_XL)     return g_xl;
    if (ID == BUF_XR)     return g_xr;
    if (ID == BUF_H)      return g_h;
    if (ID == BUF_HIDDEN) return g_hidden;
    if (ID == BUF_TMP2)   return g_tmp2;
    return (float*)ext;
}

// defensive clamp: all node indices must land in [0, TNq)
__device__ __forceinline__ int clampi(int v, int lo, int hi) {
    return v < lo ? lo : (v > hi ? hi : v);
}

// ---------------- edge_index dtype detection ----------------
// JAX silently downcasts jnp.int64 -> int32 unless x64 is enabled, so the
// buffer may be int32[2E] or int64[2E]. Inspect only the first 2E 32-bit
// words (safe under BOTH dtypes). If int64 (little-endian): odd words are the
// high halves of the first E values, all zero (values in [0,883)). If int32:
// odd words are random node ids, essentially surely not all zero.
__global__ void k_detect(const int* __restrict__ w) {
    __shared__ int any;
    if (threadIdx.x == 0) any = 0;
    __syncthreads();
    int local = 0;
    for (int k = 1 + 2 * (int)threadIdx.x; k < 2 * Eq; k += 2 * (int)blockDim.x)
        local |= w[k];
    if (local) atomicOr(&any, 1);
    __syncthreads();
    if (threadIdx.x == 0) g_is64 = (any == 0) ? 1 : 0;
}

__device__ __forceinline__ int edge_src(const int* w, int k, int is64) {
    int v = is64 ? w[2 * k] : w[k];
    return clampi(v, 0, Nq - 1);
}
__device__ __forceinline__ int edge_dst(const int* w, int k, int is64) {
    int v = is64 ? w[2 * (Eq + k)] : w[Eq + k];
    return clampi(v, 0, Nq - 1);
}

// ---------------- CSR construction ----------------
__global__ void k_zero_counts() {
    int i = blockIdx.x*blockDim.x + threadIdx.x;
    if (i < TNq) g_count[i] = 0;
}

__global__ void k_count(const int* __restrict__ ew) {
    int e = blockIdx.x*blockDim.x + threadIdx.x;
    if (e >= ETOT) return;
    const int is64 = g_is64;
    int dst;
    if (e < EEq) {
        int b = e / Eq;
        int k = e - b*Eq;
        dst = edge_dst(ew, k, is64) + b*Nq;
    } else {
        dst = e - EEq;
    }
    atomicAdd(&g_count[dst], 1);
}

__global__ void k_scan() {
    __shared__ int sh[1024];
    const int t = threadIdx.x;
    const int PER = (TNq + 1023) / 1024;   // 83
    int base = t * PER;
    int sum = 0;
    for (int i = 0; i < PER; i++) {
        int idx = base + i;
        if (idx < TNq) sum += g_count[idx];
    }
    sh[t] = sum;
    __syncthreads();
    for (int off = 1; off < 1024; off <<= 1) {
        int v = (t >= off) ? sh[t - off] : 0;
        __syncthreads();
        sh[t] += v;
        __syncthreads();
    }
    int run = sh[t] - sum;   // exclusive offset for this thread's chunk
    for (int i = 0; i < PER; i++) {
        int idx = base + i;
        if (idx < TNq) {
            g_rowptr[idx] = run;
            g_cursor[idx] = run;
            run += g_count[idx];
        }
    }
    if (t == 0) g_rowptr[TNq] = ETOT;
}

__global__ void k_scatter(const int* __restrict__ ew) {
    int e = blockIdx.x*blockDim.x + threadIdx.x;
    if (e >= ETOT) return;
    const int is64 = g_is64;
    int src, dst;
    if (e < EEq) {
        int b = e / Eq;
        int k = e - b*Eq;
        src = edge_src(ew, k, is64) + b*Nq;
        dst = edge_dst(ew, k, is64) + b*Nq;
    } else {
        src = dst = e - EEq;
    }
    int pos = atomicAdd(&g_cursor[dst], 1);
    pos = clampi(pos, 0, ETOT - 1);   // defensive: cannot escape g_esrc
    g_esrc[pos] = src;
}

// ---------------- generic fp32 tiled GEMM: C = act(A@B + bias) ----------------
// A: MxK row-major (starting at row a_off of its buffer),
// C: MxN row-major (starting at row c_off). BM=BN=64, BK=16, 256 threads, 4x4/thread.
template<int ACT, int AID, int CID>
__global__ void k_gemm(const float* __restrict__ Aext, const float* __restrict__ Bm,
                       const float* __restrict__ bias, float* __restrict__ Cext,
                       int M, int Ncols, int K, int a_off, int c_off) {
    const float* __restrict__ A  = buf_ptr<AID>(Aext) + (size_t)a_off * K;
    float* __restrict__       Cm = buf_ptr<CID>(Cext) + (size_t)c_off * Ncols;

    __shared__ float As[16][64];
    __shared__ float Bs[16][64];
    const int tid = threadIdx.x;
    const int tx = tid & 15;      // col group
    const int ty = tid >> 4;      // row group
    const int row0 = blockIdx.x * 64;
    const int col0 = blockIdx.y * 64;

    float acc[4][4];
#pragma unroll
    for (int i = 0; i < 4; i++)
#pragma unroll
        for (int j = 0; j < 4; j++) acc[i][j] = 0.f;

    for (int k0 = 0; k0 < K; k0 += 16) {
        {
            int r  = tid >> 2;
            int c4 = (tid & 3) * 4;
            int grow = row0 + r;
            float4 v = make_float4(0.f, 0.f, 0.f, 0.f);
            if (grow < M) v = *(const float4*)&A[(size_t)grow * K + k0 + c4];
            As[c4 + 0][r] = v.x;
            As[c4 + 1][r] = v.y;
            As[c4 + 2][r] = v.z;
            As[c4 + 3][r] = v.w;
        }
        {
            int r = tid >> 4;
            int c = (tid & 15) * 4;
            *(float4*)&Bs[r][c] = *(const float4*)&Bm[(size_t)(k0 + r) * Ncols + col0 + c];
        }
        __syncthreads();
#pragma unroll
        for (int kk = 0; kk < 16; kk++) {
            float4 a = *(float4*)&As[kk][ty * 4];
            float4 b = *(float4*)&Bs[kk][tx * 4];
            float av[4] = {a.x, a.y, a.z, a.w};
            float bv[4] = {b.x, b.y, b.z, b.w};
#pragma unroll
            for (int i = 0; i < 4; i++)
#pragma unroll
                for (int j = 0; j < 4; j++)
                    acc[i][j] += av[i] * bv[j];
        }
        __syncthreads();
    }

    float4 bi = *(const float4*)&bias[col0 + tx * 4];
    float bb[4] = {bi.x, bi.y, bi.z, bi.w};
#pragma unroll
    for (int i = 0; i < 4; i++) {
        int grow = row0 + ty * 4 + i;
        if (grow < M) {
            float4 o;
            float v0 = acc[i][0] + bb[0];
            float v1 = acc[i][1] + bb[1];
            float v2 = acc[i][2] + bb[2];
            float v3 = acc[i][3] + bb[3];
            if (ACT) { v0 = fmaxf(v0, 0.f); v1 = fmaxf(v1, 0.f); v2 = fmaxf(v2, 0.f); v3 = fmaxf(v3, 0.f); }
            o.x = v0; o.y = v1; o.z = v2; o.w = v3;
            *(float4*)&Cm[(size_t)grow * Ncols + col0 + tx * 4] = o;
        }
    }
}

// ---------------- fused GATv2 aggregation + residual + LN1 (one warp per node) ----------------
__global__ void k_gat(const float* __restrict__ x, const float* __restrict__ att,
                      const float* __restrict__ bias_gat,
                      const float* __restrict__ g1, const float* __restrict__ be1) {
    int warp = (blockIdx.x * blockDim.x + threadIdx.x) >> 5;
    int lane = threadIdx.x & 31;
    if (warp >= TNq) return;
    const int i = warp;

    float4 xr = *(const float4*)&g_xr[(size_t)i * Dq + lane * 4];
    float4 at = *(const float4*)&att[lane * 4];

    float m = -1e30f, s = 0.f;
    float ax = 0.f, ay = 0.f, az = 0.f, aw = 0.f;

    int beg = g_rowptr[i], end = g_rowptr[i + 1];
    for (int e = beg; e < end; e++) {
        int j = clampi(g_esrc[e], 0, TNq - 1);
        float4 xl = *(const float4*)&g_xl[(size_t)j * Dq + lane * 4];
        float t0 = xl.x + xr.x; t0 = t0 > 0.f ? t0 : NEG * t0;
        float t1 = xl.y + xr.y; t1 = t1 > 0.f ? t1 : NEG * t1;
        float t2 = xl.z + xr.z; t2 = t2 > 0.f ? t2 : NEG * t2;
        float t3 = xl.w + xr.w; t3 = t3 > 0.f ? t3 : NEG * t3;
        float p = t0 * at.x + t1 * at.y + t2 * at.z + t3 * at.w;
        p += __shfl_xor_sync(0xffffffffu, p, 1);
        p += __shfl_xor_sync(0xffffffffu, p, 2);
        float nm = fmaxf(m, p);
        float sc = __expf(m - nm);
        float w  = __expf(p - nm);
        s  = s * sc + w;
        ax = ax * sc + w * xl.x;
        ay = ay * sc + w * xl.y;
        az = az * sc + w * xl.z;
        aw = aw * sc + w * xl.w;
        m = nm;
    }
    float inv = 1.f / s;

    float4 xv = *(const float4*)&x[(size_t)i * Dq + lane * 4];
    float4 bg = *(const float4*)&bias_gat[lane * 4];
    float o0 = ax * inv + bg.x + xv.x;
    float o1 = ay * inv + bg.y + xv.y;
    float o2 = az * inv + bg.z + xv.z;
    float o3 = aw * inv + bg.w + xv.w;

    float sum = o0 + o1 + o2 + o3;
    float sq  = o0*o0 + o1*o1 + o2*o2 + o3*o3;
#pragma unroll
    for (int off = 16; off > 0; off >>= 1) {
        sum += __shfl_xor_sync(0xffffffffu, sum, off);
        sq  += __shfl_xor_sync(0xffffffffu, sq, off);
    }
    float mu  = sum * (1.f / 128.f);
    float var = sq * (1.f / 128.f) - mu * mu;
    float rs  = rsqrtf(var + 1e-5f);
    float4 gv = *(const float4*)&g1[lane * 4];
    float4 bv = *(const float4*)&be1[lane * 4];
    float4 hres;
    hres.x = (o0 - mu) * rs * gv.x + bv.x;
    hres.y = (o1 - mu) * rs * gv.y + bv.y;
    hres.z = (o2 - mu) * rs * gv.z + bv.z;
    hres.w = (o3 - mu) * rs * gv.w + bv.w;
    *(float4*)&g_h[(size_t)i * Dq + lane * 4] = hres;
}

// ---------------- final residual + LN2 -> output ----------------
__global__ void k_ln2(const float* __restrict__ g2, const float* __restrict__ be2,
                      float* __restrict__ out) {
    int warp = (blockIdx.x * blockDim.x + threadIdx.x) >> 5;
    int lane = threadIdx.x & 31;
    if (warp >= TNq) return;
    const int i = warp;
    float4 h4 = *(const float4*)&g_h   [(size_t)i * Dq + lane * 4];
    float4 t4 = *(const float4*)&g_tmp2[(size_t)i * Dq + lane * 4];
    float o0 = h4.x + t4.x;
    float o1 = h4.y + t4.y;
    float o2 = h4.z + t4.z;
    float o3 = h4.w + t4.w;
    float sum = o0 + o1 + o2 + o3;
    float sq  = o0*o0 + o1*o1 + o2*o2 + o3*o3;
#pragma unroll
    for (int off = 16; off > 0; off >>= 1) {
        sum += __shfl_xor_sync(0xffffffffu, sum, off);
        sq  += __shfl_xor_sync(0xffffffffu, sq, off);
    }
    float mu  = sum * (1.f / 128.f);
    float var = sq * (1.f / 128.f) - mu * mu;
    float rs  = rsqrtf(var + 1e-5f);
    float4 gv = *(const float4*)&g2[lane * 4];
    float4 bv = *(const float4*)&be2[lane * 4];
    float4 o;
    o.x = (o0 - mu) * rs * gv.x + bv.x;
    o.y = (o1 - mu) * rs * gv.y + bv.y;
    o.z = (o2 - mu) * rs * gv.z + bv.z;
    o.w = (o3 - mu) * rs * gv.w + bv.w;
    *(float4*)&out[(size_t)i * Dq + lane * 4] = o;
}

// ---------------- launch ----------------
extern "C" void kernel_launch(void* const* d_in, const int* in_sizes, int n_in,
                              void* d_out, int out_size) {
    const float*      x        = (const float*)d_in[0];
    const int*        ew       = (const int*)d_in[1];   // edge_index words (int32 or int64, auto-detected)
    const float*      Wl       = (const float*)d_in[2];
    const float*      bl       = (const float*)d_in[3];
    const float*      Wr       = (const float*)d_in[4];
    const float*      br       = (const float*)d_in[5];
    const float*      att      = (const float*)d_in[6];
    const float*      bias_gat = (const float*)d_in[7];
    const float*      W1       = (const float*)d_in[8];
    const float*      b1       = (const float*)d_in[9];
    const float*      W2       = (const float*)d_in[10];
    const float*      b2       = (const float*)d_in[11];
    const float*      g1       = (const float*)d_in[12];
    const float*      be1      = (const float*)d_in[13];
    const float*      g2       = (const float*)d_in[14];
    const float*      be2      = (const float*)d_in[15];
    float*            out      = (float*)d_out;

    // dtype detection + CSR build
    k_detect<<<1, 1024>>>(ew);
    k_zero_counts<<<(TNq + 255) / 256, 256>>>();
    k_count<<<(ETOT + 255) / 256, 256>>>(ew);
    k_scan<<<1, 1024>>>();
    k_scatter<<<(ETOT + 255) / 256, 256>>>(ew);

    const int MB = (TNq + 63) / 64;   // 1325 row blocks

    // x_l = x@Wl + bl ; x_r = x@Wr + br
    k_gemm<0, BUF_EXT, BUF_XL><<<dim3(MB, 2), 256>>>(x, Wl, bl, nullptr, TNq, Dq, Dq, 0, 0);
    k_gemm<0, BUF_EXT, BUF_XR><<<dim3(MB, 2), 256>>>(x, Wr, br, nullptr, TNq, Dq, Dq, 0, 0);

    // fused GATv2 softmax-aggregate + residual + LN1 -> g_h
    k_gat<<<(TNq * 32 + 255) / 256, 256>>>(x, att, bias_gat, g1, be1);

    // FFN, sliced over M to reuse one small hidden buffer
    const int MBS = (SLQ + 63) / 64;  // 166 row blocks per slice
    for (int s = 0; s < NSLICE; s++) {
        int r0 = s * SLQ;
        k_gemm<1, BUF_H,      BUF_HIDDEN><<<dim3(MBS, FFq / 64), 256>>>(nullptr, W1, b1, nullptr, SLQ, FFq, Dq,  r0, 0);
        k_gemm<0, BUF_HIDDEN, BUF_TMP2  ><<<dim3(MBS, Dq  / 64), 256>>>(nullptr, W2, b2, nullptr, SLQ, Dq,  FFq, 0,  r0);
    }

    // residual + LN2 -> out
    k_ln2<<<(TNq * 32 + 255) / 256, 256>>>(g2, be2, out);
}

// round 11
// speedup vs baseline: 1.4027x; 1.4027x over previous
#include <cuda_runtime.h>
#include <cuda_bf16.h>
#include <cstdint>

// ---------------- problem constants ----------------
#define Bq   8
#define Tq   12
#define Nq   883
#define Dq   128
#define Eq   7000
#define FFq  2048
#define BTq  (Bq*Tq)            // 96
#define TNq  (BTq*Nq)           // 84768
#define EEq  (BTq*Eq)           // 672000
#define ETOT (EEq+TNq)          // 756768
#define NEG  0.2f

#define NSLICE 2
#define SLQ    (TNq / NSLICE)   // 42384

// ---------------- scratch (device globals; no allocations allowed) ----------------
__device__ float g_xl[(size_t)TNq*Dq];
__device__ float g_xr[(size_t)TNq*Dq];
__device__ float g_h [(size_t)TNq*Dq];
__device__ float g_hidden[(size_t)SLQ*FFq];
__device__ float g_tmp2[(size_t)TNq*Dq];
__device__ int   g_count[TNq];
__device__ int   g_rowptr[TNq+1];
__device__ int   g_cursor[TNq];
__device__ int   g_esrc[ETOT];
__device__ int   g_is64;
__device__ int   g_bsum[128];

#define BUF_EXT    0
#define BUF_XL     1
#define BUF_XR     2
#define BUF_H      3
#define BUF_HIDDEN 4
#define BUF_TMP2   5

template<int ID>
__device__ __forceinline__ float* buf_ptr(const float* ext) {
    if (ID == BUF_XL)     return g_xl;
    if (ID == BUF_XR)     return g_xr;
    if (ID == BUF_H)      return g_h;
    if (ID == BUF_HIDDEN) return g_hidden;
    if (ID == BUF_TMP2)   return g_tmp2;
    return (float*)ext;
}

__device__ __forceinline__ int clampi(int v, int lo, int hi) {
    return v < lo ? lo : (v > hi ? hi : v);
}

__device__ __forceinline__ uint32_t smem_u32(const void* p) {
    uint32_t a;
    asm("{ .reg .u64 t; cvta.to.shared.u64 t, %1; cvt.u32.u64 %0, t; }" : "=r"(a) : "l"(p));
    return a;
}

// bf16 two-term split helpers
__device__ __forceinline__ void split2(float a, float b, uint32_t& hi, uint32_t& lo) {
    __nv_bfloat16 ha = __float2bfloat16(a), hb = __float2bfloat16(b);
    __nv_bfloat16 la = __float2bfloat16(a - __bfloat162float(ha));
    __nv_bfloat16 lb = __float2bfloat16(b - __bfloat162float(hb));
    hi = (uint32_t)__bfloat16_as_ushort(ha) | ((uint32_t)__bfloat16_as_ushort(hb) << 16);
    lo = (uint32_t)__bfloat16_as_ushort(la) | ((uint32_t)__bfloat16_as_ushort(lb) << 16);
}
__device__ __forceinline__ void split1(float a, unsigned short& h, unsigned short& l) {
    __nv_bfloat16 ha = __float2bfloat16(a);
    h = __bfloat16_as_ushort(ha);
    l = __bfloat16_as_ushort(__float2bfloat16(a - __bfloat162float(ha)));
}

__device__ __forceinline__ void ldmx4(uint32_t* r, uint32_t addr) {
    asm volatile("ldmatrix.sync.aligned.m8n8.x4.shared.b16 {%0,%1,%2,%3}, [%4];"
                 : "=r"(r[0]), "=r"(r[1]), "=r"(r[2]), "=r"(r[3]) : "r"(addr));
}
__device__ __forceinline__ void mma16816(float* c, const uint32_t* a, uint32_t b0, uint32_t b1) {
    asm volatile(
        "mma.sync.aligned.m16n8k16.row.col.f32.bf16.bf16.f32 "
        "{%0,%1,%2,%3}, {%4,%5,%6,%7}, {%8,%9}, {%0,%1,%2,%3};"
        : "+f"(c[0]), "+f"(c[1]), "+f"(c[2]), "+f"(c[3])
        : "r"(a[0]), "r"(a[1]), "r"(a[2]), "r"(a[3]), "r"(b0), "r"(b1));
}

// ---------------- edge_index dtype detection ----------------
__global__ void k_detect(const int* __restrict__ w) {
    __shared__ int any;
    if (threadIdx.x == 0) any = 0;
    __syncthreads();
    int local = 0;
    for (int k = 1 + 2 * (int)threadIdx.x; k < 2 * Eq; k += 2 * (int)blockDim.x)
        local |= w[k];
    if (local) atomicOr(&any, 1);
    __syncthreads();
    if (threadIdx.x == 0) g_is64 = (any == 0) ? 1 : 0;
}
__device__ __forceinline__ int edge_src(const int* w, int k, int is64) {
    int v = is64 ? w[2 * k] : w[k];
    return clampi(v, 0, Nq - 1);
}
__device__ __forceinline__ int edge_dst(const int* w, int k, int is64) {
    int v = is64 ? w[2 * (Eq + k)] : w[Eq + k];
    return clampi(v, 0, Nq - 1);
}

// ---------------- CSR construction ----------------
__global__ void k_zero_counts() {
    int i = blockIdx.x*blockDim.x + threadIdx.x;
    if (i < TNq) g_count[i] = 0;
}
__global__ void k_count(const int* __restrict__ ew) {
    int e = blockIdx.x*blockDim.x + threadIdx.x;
    if (e >= ETOT) return;
    const int is64 = g_is64;
    int dst;
    if (e < EEq) {
        int b = e / Eq;
        int k = e - b*Eq;
        dst = edge_dst(ew, k, is64) + b*Nq;
    } else {
        dst = e - EEq;
    }
    atomicAdd(&g_count[dst], 1);
}

#define SCANB ((TNq + 1023) / 1024)   // 83
__global__ void k_scan1() {
    __shared__ int red[1024];
    int t = threadIdx.x;
    int idx = blockIdx.x * 1024 + t;
    int v = (idx < TNq) ? g_count[idx] : 0;
    red[t] = v;
    __syncthreads();
    for (int off = 512; off > 0; off >>= 1) {
        if (t < off) red[t] += red[t + off];
        __syncthreads();
    }
    if (t == 0) g_bsum[blockIdx.x] = red[0];
}
__global__ void k_scan2() {
    __shared__ int s[128];
    int t = threadIdx.x;
    int v = (t < SCANB) ? g_bsum[t] : 0;
    s[t] = v;
    __syncthreads();
    for (int off = 1; off < 128; off <<= 1) {
        int u = (t >= off) ? s[t - off] : 0;
        __syncthreads();
        s[t] += u;
        __syncthreads();
    }
    if (t < SCANB) g_bsum[t] = s[t] - v;
}
__global__ void k_scan3() {
    __shared__ int s[1024];
    int t = threadIdx.x;
    int idx = blockIdx.x * 1024 + t;
    int v = (idx < TNq) ? g_count[idx] : 0;
    s[t] = v;
    __syncthreads();
    for (int off = 1; off < 1024; off <<= 1) {
        int u = (t >= off) ? s[t - off] : 0;
        __syncthreads();
        s[t] += u;
        __syncthreads();
    }
    int ex = g_bsum[blockIdx.x] + s[t] - v;
    if (idx < TNq) { g_rowptr[idx] = ex; g_cursor[idx] = ex; }
    if (blockIdx.x == 0 && t == 0) g_rowptr[TNq] = ETOT;
}

__global__ void k_scatter(const int* __restrict__ ew) {
    int e = blockIdx.x*blockDim.x + threadIdx.x;
    if (e >= ETOT) return;
    const int is64 = g_is64;
    int src, dst;
    if (e < EEq) {
        int b = e / Eq;
        int k = e - b*Eq;
        src = edge_src(ew, k, is64) + b*Nq;
        dst = edge_dst(ew, k, is64) + b*Nq;
    } else {
        src = dst = e - EEq;
    }
    int pos = atomicAdd(&g_cursor[dst], 1);
    pos = clampi(pos, 0, ETOT - 1);
    g_esrc[pos] = src;
}

// ---------------- HMMA (mma.sync) GEMM: C = act(A@B + bias) ----------------
// bf16 two-term split (Ah*Bh + Al*Bh + Ah*Bl), fp32 accumulate.
// Block tile 128x128, K chunks of 32. 8 warps = 4(M) x 2(N); warp tile 32x64.
// A: MxK row-major; B: KxN row-major; C: MxN.
#define SPITCH 40   // bf16 elems per smem row (80B: 16B-aligned rows for ldmatrix; 20-bank stride, conflict-free)
template<int ACT, int AID, int CID>
__global__ void __launch_bounds__(256, 1)
k_tgemm(const float* __restrict__ Aext, const float* __restrict__ Bg,
        const float* __restrict__ bias, float* __restrict__ Cext,
        int M, int Ncols, int K, int a_off, int c_off) {
    const float* __restrict__ A = buf_ptr<AID>(Aext) + (size_t)a_off * K;
    float* __restrict__       C = buf_ptr<CID>(Cext) + (size_t)c_off * Ncols;

    __shared__ __align__(16) __nv_bfloat16 sAh[128 * SPITCH];
    __shared__ __align__(16) __nv_bfloat16 sAl[128 * SPITCH];
    __shared__ __align__(16) __nv_bfloat16 sBh[128 * SPITCH];   // [n][k]
    __shared__ __align__(16) __nv_bfloat16 sBl[128 * SPITCH];

    const int tid  = threadIdx.x;
    const int warp = tid >> 5;
    const int lane = tid & 31;
    const int wm   = warp >> 1;     // 0..3  (32 rows each)
    const int wn   = warp & 1;      // 0..1  (64 cols each)
    const int row0 = blockIdx.x * 128;
    const int col0 = blockIdx.y * 128;

    float acc[2][8][4];
#pragma unroll
    for (int mt = 0; mt < 2; mt++)
#pragma unroll
        for (int nt = 0; nt < 8; nt++)
#pragma unroll
            for (int q = 0; q < 4; q++) acc[mt][nt][q] = 0.f;

    // ldmatrix addressing
    const int aRow = wm * 32 + (lane & 15);
    const int aColOff = ((lane >> 4) & 1) * 8;
    const int bRowBase = wn * 64 + (lane & 7) + (((lane >> 4) & 1) << 3);
    const int bColOff  = ((lane >> 3) & 1) * 8;

    const int NC = K >> 5;
    for (int c = 0; c < NC; c++) {
        const int k0g = c << 5;

        // ---- load A chunk [128 x 32] fp32 -> split -> sAh/sAl ----
        {
            int r  = tid >> 1;
            int hf = tid & 1;
            bool ok = (row0 + r) < M;
            const float* ap = A + (size_t)(row0 + r) * K + k0g + hf * 16;
            __nv_bfloat16* dh = sAh + r * SPITCH + hf * 16;
            __nv_bfloat16* dl = sAl + r * SPITCH + hf * 16;
#pragma unroll
            for (int q = 0; q < 4; q++) {
                float4 v = ok ? *(const float4*)(ap + 4 * q) : make_float4(0.f,0.f,0.f,0.f);
                uint32_t h0, l0, h1, l1;
                split2(v.x, v.y, h0, l0);
                split2(v.z, v.w, h1, l1);
                *(uint32_t*)(dh + 4 * q)     = h0;
                *(uint32_t*)(dh + 4 * q + 2) = h1;
                *(uint32_t*)(dl + 4 * q)     = l0;
                *(uint32_t*)(dl + 4 * q + 2) = l1;
            }
        }
        // ---- load B chunk [32 x 128], transpose -> sBh/sBl [n][k] ----
        {
            int kk = tid >> 3;            // 0..31
            int n0 = (tid & 7) * 16;      // 16 n-values
            const float* bp = Bg + (size_t)(k0g + kk) * Ncols + col0 + n0;
#pragma unroll
            for (int q = 0; q < 4; q++) {
                float4 v = *(const float4*)(bp + 4 * q);
                int nb = n0 + 4 * q;
                unsigned short h, l;
                split1(v.x, h, l); sBh[(nb+0)*SPITCH + kk] = __ushort_as_bfloat16(h); sBl[(nb+0)*SPITCH + kk] = __ushort_as_bfloat16(l);
                split1(v.y, h, l); sBh[(nb+1)*SPITCH + kk] = __ushort_as_bfloat16(h); sBl[(nb+1)*SPITCH + kk] = __ushort_as_bfloat16(l);
                split1(v.z, h, l); sBh[(nb+2)*SPITCH + kk] = __ushort_as_bfloat16(h); sBl[(nb+2)*SPITCH + kk] = __ushort_as_bfloat16(l);
                split1(v.w, h, l); sBh[(nb+3)*SPITCH + kk] = __ushort_as_bfloat16(h); sBl[(nb+3)*SPITCH + kk] = __ushort_as_bfloat16(l);
            }
        }
        __syncthreads();

        // ---- compute: 2 k-steps of 16 ----
#pragma unroll
        for (int ks = 0; ks < 2; ks++) {
            const int k0 = ks * 16;
            uint32_t ah[2][4], al[2][4];
#pragma unroll
            for (int mt = 0; mt < 2; mt++) {
                uint32_t offA = (uint32_t)(((aRow + mt * 16) * SPITCH + k0 + aColOff) * 2);
                ldmx4(ah[mt], smem_u32(sAh) + offA);
                ldmx4(al[mt], smem_u32(sAl) + offA);
            }
            uint32_t bh[4][4], bl[4][4];
#pragma unroll
            for (int np = 0; np < 4; np++) {
                uint32_t offB = (uint32_t)(((bRowBase + np * 16) * SPITCH + k0 + bColOff) * 2);
                ldmx4(bh[np], smem_u32(sBh) + offB);
                ldmx4(bl[np], smem_u32(sBl) + offB);
            }
#pragma unroll
            for (int mt = 0; mt < 2; mt++)
#pragma unroll
                for (int nt = 0; nt < 8; nt++) {
                    int np = nt >> 1, od = (nt & 1) * 2;
                    mma16816(acc[mt][nt], ah[mt], bh[np][od], bh[np][od + 1]);
                    mma16816(acc[mt][nt], al[mt], bh[np][od], bh[np][od + 1]);
                    mma16816(acc[mt][nt], ah[mt], bl[np][od], bl[np][od + 1]);
                }
        }
        __syncthreads();
    }

    // ---- epilogue ----
#pragma unroll
    for (int mt = 0; mt < 2; mt++) {
        int r0 = row0 + wm * 32 + mt * 16 + (lane >> 2);
#pragma unroll
        for (int nt = 0; nt < 8; nt++) {
            int cb = col0 + wn * 64 + nt * 8 + (lane & 3) * 2;
            float b0 = bias[cb], b1 = bias[cb + 1];
            float v0 = acc[mt][nt][0] + b0, v1 = acc[mt][nt][1] + b1;
            float v2 = acc[mt][nt][2] + b0, v3 = acc[mt][nt][3] + b1;
            if (ACT) {
                v0 = fmaxf(v0, 0.f); v1 = fmaxf(v1, 0.f);
                v2 = fmaxf(v2, 0.f); v3 = fmaxf(v3, 0.f);
            }
            if (r0 < M)     *(float2*)&C[(size_t)r0 * Ncols + cb]       = make_float2(v0, v1);
            if (r0 + 8 < M) *(float2*)&C[(size_t)(r0 + 8) * Ncols + cb] = make_float2(v2, v3);
        }
    }
}

// ---------------- fused GATv2 aggregation + residual + LN1 (one warp per node) ----------------
__global__ void k_gat(const float* __restrict__ x, const float* __restrict__ att,
                      const float* __restrict__ bias_gat,
                      const float* __restrict__ g1, const float* __restrict__ be1) {
    int warp = (blockIdx.x * blockDim.x + threadIdx.x) >> 5;
    int lane = threadIdx.x & 31;
    if (warp >= TNq) return;
    const int i = warp;

    float4 xr = *(const float4*)&g_xr[(size_t)i * Dq + lane * 4];
    float4 at = *(const float4*)&att[lane * 4];

    float m = -1e30f, s = 0.f;
    float ax = 0.f, ay = 0.f, az = 0.f, aw = 0.f;

    int beg = g_rowptr[i], end = g_rowptr[i + 1];
    for (int e = beg; e < end; e++) {
        int j = clampi(g_esrc[e], 0, TNq - 1);
        float4 xl = *(const float4*)&g_xl[(size_t)j * Dq + lane * 4];
        float t0 = xl.x + xr.x; t0 = t0 > 0.f ? t0 : NEG * t0;
        float t1 = xl.y + xr.y; t1 = t1 > 0.f ? t1 : NEG * t1;
        float t2 = xl.z + xr.z; t2 = t2 > 0.f ? t2 : NEG * t2;
        float t3 = xl.w + xr.w; t3 = t3 > 0.f ? t3 : NEG * t3;
        float p = t0 * at.x + t1 * at.y + t2 * at.z + t3 * at.w;
        p += __shfl_xor_sync(0xffffffffu, p, 1);
        p += __shfl_xor_sync(0xffffffffu, p, 2);
        float nm = fmaxf(m, p);
        float sc = __expf(m - nm);
        float w  = __expf(p - nm);
        s  = s * sc + w;
        ax = ax * sc + w * xl.x;
        ay = ay * sc + w * xl.y;
        az = az * sc + w * xl.z;
        aw = aw * sc + w * xl.w;
        m = nm;
    }
    float inv = 1.f / s;

    float4 xv = *(const float4*)&x[(size_t)i * Dq + lane * 4];
    float4 bg = *(const float4*)&bias_gat[lane * 4];
    float o0 = ax * inv + bg.x + xv.x;
    float o1 = ay * inv + bg.y + xv.y;
    float o2 = az * inv + bg.z + xv.z;
    float o3 = aw * inv + bg.w + xv.w;

    float sum = o0 + o1 + o2 + o3;
    float sq  = o0*o0 + o1*o1 + o2*o2 + o3*o3;
#pragma unroll
    for (int off = 16; off > 0; off >>= 1) {
        sum += __shfl_xor_sync(0xffffffffu, sum, off);
        sq  += __shfl_xor_sync(0xffffffffu, sq, off);
    }
    float mu  = sum * (1.f / 128.f);
    float var = sq * (1.f / 128.f) - mu * mu;
    float rs  = rsqrtf(var + 1e-5f);
    float4 gv = *(const float4*)&g1[lane * 4];
    float4 bv = *(const float4*)&be1[lane * 4];
    float4 hres;
    hres.x = (o0 - mu) * rs * gv.x + bv.x;
    hres.y = (o1 - mu) * rs * gv.y + bv.y;
    hres.z = (o2 - mu) * rs * gv.z + bv.z;
    hres.w = (o3 - mu) * rs * gv.w + bv.w;
    *(float4*)&g_h[(size_t)i * Dq + lane * 4] = hres;
}

// ---------------- final residual + LN2 -> output ----------------
__global__ void k_ln2(const float* __restrict__ g2, const float* __restrict__ be2,
                      float* __restrict__ out) {
    int warp = (blockIdx.x * blockDim.x + threadIdx.x) >> 5;
    int lane = threadIdx.x & 31;
    if (warp >= TNq) return;
    const int i = warp;
    float4 h4 = *(const float4*)&g_h   [(size_t)i * Dq + lane * 4];
    float4 t4 = *(const float4*)&g_tmp2[(size_t)i * Dq + lane * 4];
    float o0 = h4.x + t4.x;
    float o1 = h4.y + t4.y;
    float o2 = h4.z + t4.z;
    float o3 = h4.w + t4.w;
    float sum = o0 + o1 + o2 + o3;
    float sq  = o0*o0 + o1*o1 + o2*o2 + o3*o3;
#pragma unroll
    for (int off = 16; off > 0; off >>= 1) {
        sum += __shfl_xor_sync(0xffffffffu, sum, off);
        sq  += __shfl_xor_sync(0xffffffffu, sq, off);
    }
    float mu  = sum * (1.f / 128.f);
    float var = sq * (1.f / 128.f) - mu * mu;
    float rs  = rsqrtf(var + 1e-5f);
    float4 gv = *(const float4*)&g2[lane * 4];
    float4 bv = *(const float4*)&be2[lane * 4];
    float4 o;
    o.x = (o0 - mu) * rs * gv.x + bv.x;
    o.y = (o1 - mu) * rs * gv.y + bv.y;
    o.z = (o2 - mu) * rs * gv.z + bv.z;
    o.w = (o3 - mu) * rs * gv.w + bv.w;
    *(float4*)&out[(size_t)i * Dq + lane * 4] = o;
}

// ---------------- launch ----------------
extern "C" void kernel_launch(void* const* d_in, const int* in_sizes, int n_in,
                              void* d_out, int out_size) {
    const float* x        = (const float*)d_in[0];
    const int*   ew       = (const int*)d_in[1];
    const float* Wl       = (const float*)d_in[2];
    const float* bl       = (const float*)d_in[3];
    const float* Wr       = (const float*)d_in[4];
    const float* br       = (const float*)d_in[5];
    const float* att      = (const float*)d_in[6];
    const float* bias_gat = (const float*)d_in[7];
    const float* W1       = (const float*)d_in[8];
    const float* b1       = (const float*)d_in[9];
    const float* W2       = (const float*)d_in[10];
    const float* b2       = (const float*)d_in[11];
    const float* g1       = (const float*)d_in[12];
    const float* be1      = (const float*)d_in[13];
    const float* g2       = (const float*)d_in[14];
    const float* be2      = (const float*)d_in[15];
    float*       out      = (float*)d_out;

    // dtype detection + CSR build
    k_detect<<<1, 1024>>>(ew);
    k_zero_counts<<<(TNq + 255) / 256, 256>>>();
    k_count<<<(ETOT + 255) / 256, 256>>>(ew);
    k_scan1<<<SCANB, 1024>>>();
    k_scan2<<<1, 128>>>();
    k_scan3<<<SCANB, 1024>>>();
    k_scatter<<<(ETOT + 255) / 256, 256>>>(ew);

    const int MT = (TNq + 127) / 128;   // 663 M-tiles

    // x_l = x@Wl + bl ; x_r = x@Wr + br (HMMA)
    k_tgemm<0, BUF_EXT, BUF_XL><<<dim3(MT, 1), 256>>>(x, Wl, bl, nullptr, TNq, Dq, Dq, 0, 0);
    k_tgemm<0, BUF_EXT, BUF_XR><<<dim3(MT, 1), 256>>>(x, Wr, br, nullptr, TNq, Dq, Dq, 0, 0);

    // fused GATv2 softmax-aggregate + residual + LN1 -> g_h
    k_gat<<<(TNq * 32 + 255) / 256, 256>>>(x, att, bias_gat, g1, be1);

    // FFN (HMMA), sliced over M
    const int MTS = (SLQ + 127) / 128;  // 332 M-tiles per slice
    for (int s = 0; s < NSLICE; s++) {
        int r0 = s * SLQ;
        k_tgemm<1, BUF_H,      BUF_HIDDEN><<<dim3(MTS, FFq / 128), 256>>>(nullptr, W1, b1, nullptr, SLQ, FFq, Dq,  r0, 0);
        k_tgemm<0, BUF_HIDDEN, BUF_TMP2  ><<<dim3(MTS, Dq  / 128), 256>>>(nullptr, W2, b2, nullptr, SLQ, Dq,  FFq, 0,  r0);
    }

    // residual + LN2 -> out
    k_ln2<<<(TNq * 32 + 255) / 256, 256>>>(g2, be2, out);
}

// round 12
// speedup vs baseline: 2.1878x; 1.5597x over previous
#include <cuda_runtime.h>
#include <cuda_bf16.h>
#include <cstdint>

// ---------------- problem constants ----------------
#define Bq   8
#define Tq   12
#define Nq   883
#define Dq   128
#define Eq   7000
#define FFq  2048
#define BTq  (Bq*Tq)            // 96
#define TNq  (BTq*Nq)           // 84768
#define EEq  (BTq*Eq)           // 672000
#define ETOT (EEq+TNq)          // 756768
#define NEG  0.2f

#define NSLICE 2
#define SLQ    (TNq / NSLICE)   // 42384

// weight-transpose buffer offsets ([N][K] bf16 hi/lo)
#define OFF_WL 0
#define OFF_WR (128*128)
#define OFF_W1 (2*128*128)                 // 32768, N=2048 x K=128
#define OFF_W2 (OFF_W1 + 2048*128)         // 294912, N=128 x K=2048
#define WT_TOT (OFF_W2 + 128*2048)         // 557056

// ---------------- scratch (device globals; no allocations allowed) ----------------
__device__ float g_xl[(size_t)TNq*Dq];
__device__ float g_xr[(size_t)TNq*Dq];
__device__ float g_h [(size_t)TNq*Dq];
__device__ float g_tmp2[(size_t)TNq*Dq];
__device__ __nv_bfloat16 g_xh [(size_t)TNq*Dq];
__device__ __nv_bfloat16 g_xlo[(size_t)TNq*Dq];
__device__ __nv_bfloat16 g_hh [(size_t)TNq*Dq];
__device__ __nv_bfloat16 g_hl [(size_t)TNq*Dq];
__device__ __nv_bfloat16 g_hidh[(size_t)SLQ*FFq];   // ~174MB
__device__ __nv_bfloat16 g_hidl[(size_t)SLQ*FFq];   // ~174MB
__device__ __nv_bfloat16 g_wth[WT_TOT];
__device__ __nv_bfloat16 g_wtl[WT_TOT];
__device__ int   g_count[TNq];
__device__ int   g_rowptr[TNq+1];
__device__ int   g_cursor[TNq];
__device__ int   g_esrc[ETOT];
__device__ int   g_is64;
__device__ int   g_bsum[128];

__device__ __forceinline__ int clampi(int v, int lo, int hi) {
    return v < lo ? lo : (v > hi ? hi : v);
}
__device__ __forceinline__ uint32_t smem_u32(const void* p) {
    uint32_t a;
    asm("{ .reg .u64 t; cvta.to.shared.u64 t, %1; cvt.u32.u64 %0, t; }" : "=r"(a) : "l"(p));
    return a;
}
__device__ __forceinline__ void split1(float a, unsigned short& h, unsigned short& l) {
    __nv_bfloat16 ha = __float2bfloat16(a);
    h = __bfloat16_as_ushort(ha);
    l = __bfloat16_as_ushort(__float2bfloat16(a - __bfloat162float(ha)));
}
__device__ __forceinline__ void ldmx4(uint32_t* r, uint32_t addr) {
    asm volatile("ldmatrix.sync.aligned.m8n8.x4.shared.b16 {%0,%1,%2,%3}, [%4];"
                 : "=r"(r[0]), "=r"(r[1]), "=r"(r[2]), "=r"(r[3]) : "r"(addr));
}
__device__ __forceinline__ void mma16816(float* c, const uint32_t* a, uint32_t b0, uint32_t b1) {
    asm volatile(
        "mma.sync.aligned.m16n8k16.row.col.f32.bf16.bf16.f32 "
        "{%0,%1,%2,%3}, {%4,%5,%6,%7}, {%8,%9}, {%0,%1,%2,%3};"
        : "+f"(c[0]), "+f"(c[1]), "+f"(c[2]), "+f"(c[3])
        : "r"(a[0]), "r"(a[1]), "r"(a[2]), "r"(a[3]), "r"(b0), "r"(b1));
}

// ---------------- edge_index dtype detection ----------------
__global__ void k_detect(const int* __restrict__ w) {
    __shared__ int any;
    if (threadIdx.x == 0) any = 0;
    __syncthreads();
    int local = 0;
    for (int k = 1 + 2 * (int)threadIdx.x; k < 2 * Eq; k += 2 * (int)blockDim.x)
        local |= w[k];
    if (local) atomicOr(&any, 1);
    __syncthreads();
    if (threadIdx.x == 0) g_is64 = (any == 0) ? 1 : 0;
}
__device__ __forceinline__ int edge_src(const int* w, int k, int is64) {
    int v = is64 ? w[2 * k] : w[k];
    return clampi(v, 0, Nq - 1);
}
__device__ __forceinline__ int edge_dst(const int* w, int k, int is64) {
    int v = is64 ? w[2 * (Eq + k)] : w[Eq + k];
    return clampi(v, 0, Nq - 1);
}

// ---------------- CSR construction ----------------
__global__ void k_zero_counts() {
    int i = blockIdx.x*blockDim.x + threadIdx.x;
    if (i < TNq) g_count[i] = 0;
}
__global__ void k_count(const int* __restrict__ ew) {
    int e = blockIdx.x*blockDim.x + threadIdx.x;
    if (e >= ETOT) return;
    const int is64 = g_is64;
    int dst;
    if (e < EEq) {
        int b = e / Eq;
        int k = e - b*Eq;
        dst = edge_dst(ew, k, is64) + b*Nq;
    } else {
        dst = e - EEq;
    }
    atomicAdd(&g_count[dst], 1);
}

#define SCANB ((TNq + 1023) / 1024)   // 83
__global__ void k_scan1() {
    __shared__ int red[1024];
    int t = threadIdx.x;
    int idx = blockIdx.x * 1024 + t;
    int v = (idx < TNq) ? g_count[idx] : 0;
    red[t] = v;
    __syncthreads();
    for (int off = 512; off > 0; off >>= 1) {
        if (t < off) red[t] += red[t + off];
        __syncthreads();
    }
    if (t == 0) g_bsum[blockIdx.x] = red[0];
}
__global__ void k_scan2() {
    __shared__ int s[128];
    int t = threadIdx.x;
    int v = (t < SCANB) ? g_bsum[t] : 0;
    s[t] = v;
    __syncthreads();
    for (int off = 1; off < 128; off <<= 1) {
        int u = (t >= off) ? s[t - off] : 0;
        __syncthreads();
        s[t] += u;
        __syncthreads();
    }
    if (t < SCANB) g_bsum[t] = s[t] - v;
}
__global__ void k_scan3() {
    __shared__ int s[1024];
    int t = threadIdx.x;
    int idx = blockIdx.x * 1024 + t;
    int v = (idx < TNq) ? g_count[idx] : 0;
    s[t] = v;
    __syncthreads();
    for (int off = 1; off < 1024; off <<= 1) {
        int u = (t >= off) ? s[t - off] : 0;
        __syncthreads();
        s[t] += u;
        __syncthreads();
    }
    int ex = g_bsum[blockIdx.x] + s[t] - v;
    if (idx < TNq) { g_rowptr[idx] = ex; g_cursor[idx] = ex; }
    if (blockIdx.x == 0 && t == 0) g_rowptr[TNq] = ETOT;
}

__global__ void k_scatter(const int* __restrict__ ew) {
    int e = blockIdx.x*blockDim.x + threadIdx.x;
    if (e >= ETOT) return;
    const int is64 = g_is64;
    int src, dst;
    if (e < EEq) {
        int b = e / Eq;
        int k = e - b*Eq;
        src = edge_src(ew, k, is64) + b*Nq;
        dst = edge_dst(ew, k, is64) + b*Nq;
    } else {
        src = dst = e - EEq;
    }
    int pos = atomicAdd(&g_cursor[dst], 1);
    pos = clampi(pos, 0, ETOT - 1);
    g_esrc[pos] = src;
}

// ---------------- weight transpose + split: Wt[n][k] = split(W[k][n]) ----------------
__global__ void k_prep_w(const float* __restrict__ Wl, const float* __restrict__ Wr,
                         const float* __restrict__ W1, const float* __restrict__ W2) {
    int idx = blockIdx.x * blockDim.x + threadIdx.x;
    if (idx >= WT_TOT) return;
    float v;
    if (idx < OFF_WR) {                       // Wl: [128][128] -> [n][k]
        int q = idx - OFF_WL, n = q >> 7, k = q & 127;
        v = Wl[k * 128 + n];
    } else if (idx < OFF_W1) {                // Wr
        int q = idx - OFF_WR, n = q >> 7, k = q & 127;
        v = Wr[k * 128 + n];
    } else if (idx < OFF_W2) {                // W1: [128][2048] -> [2048][128]
        int q = idx - OFF_W1, n = q >> 7, k = q & 127;
        v = W1[k * 2048 + n];
    } else {                                  // W2: [2048][128] -> [128][2048]
        int q = idx - OFF_W2, n = q >> 11, k = q & 2047;
        v = W2[k * 128 + n];
    }
    unsigned short h, l;
    split1(v, h, l);
    g_wth[idx] = __ushort_as_bfloat16(h);
    g_wtl[idx] = __ushort_as_bfloat16(l);
}

// ---------------- split x into bf16 hi/lo ----------------
__global__ void k_split_x(const float* __restrict__ x) {
    size_t i = (size_t)(blockIdx.x * blockDim.x + threadIdx.x) * 4;
    if (i >= (size_t)TNq * Dq) return;
    float4 v = *(const float4*)&x[i];
    unsigned short h0,l0,h1,l1,h2,l2,h3,l3;
    split1(v.x, h0, l0); split1(v.y, h1, l1);
    split1(v.z, h2, l2); split1(v.w, h3, l3);
    uint2 ph = make_uint2((uint32_t)h0 | ((uint32_t)h1 << 16), (uint32_t)h2 | ((uint32_t)h3 << 16));
    uint2 pl = make_uint2((uint32_t)l0 | ((uint32_t)l1 << 16), (uint32_t)l2 | ((uint32_t)l3 << 16));
    *(uint2*)&g_xh[i]  = ph;
    *(uint2*)&g_xlo[i] = pl;
}

// ---------------- HMMA GEMM, bf16-split operands pre-materialized ----------------
// A: [M][K] bf16 (hi/lo pair by AID), B: [N][K] bf16 (pre-transposed weights at wt_off),
// C: fp32 (OMODE 0, buffer by CID) or relu-split-bf16 to hidden (OMODE 1).
// Tile 128x128, K chunks of 32, 8 warps = 4(M) x 2(N).
#define SPITCH 40
// A-source IDs
#define ASRC_X   0
#define ASRC_H   1
#define ASRC_HID 2
// fp32 C IDs
#define COUT_XL   0
#define COUT_XR   1
#define COUT_TMP2 2
template<int ACT, int AID, int OMODE, int CID>
__global__ void __launch_bounds__(256, 2)
k_tgemm(const float* __restrict__ bias, int M, int Ncols, int K, int a_off, int c_off) {
    const __nv_bfloat16* Ah;
    const __nv_bfloat16* Al;
    if (AID == ASRC_X)      { Ah = g_xh;   Al = g_xlo; }
    else if (AID == ASRC_H) { Ah = g_hh;   Al = g_hl; }
    else                    { Ah = g_hidh; Al = g_hidl; }
    Ah += (size_t)a_off * K;
    Al += (size_t)a_off * K;
    int wt_off = (AID == ASRC_X) ? (CID == COUT_XL ? OFF_WL : OFF_WR)
               : (AID == ASRC_H) ? OFF_W1 : OFF_W2;
    const __nv_bfloat16* __restrict__ Bh = g_wth + wt_off;
    const __nv_bfloat16* __restrict__ Bl = g_wtl + wt_off;
    float* Cf = (CID == COUT_XL) ? g_xl : (CID == COUT_XR) ? g_xr : g_tmp2;
    Cf += (size_t)c_off * Ncols;

    __shared__ __align__(16) __nv_bfloat16 sAh[128 * SPITCH];
    __shared__ __align__(16) __nv_bfloat16 sAl[128 * SPITCH];
    __shared__ __align__(16) __nv_bfloat16 sBh[128 * SPITCH];   // [n][k]
    __shared__ __align__(16) __nv_bfloat16 sBl[128 * SPITCH];

    const int tid  = threadIdx.x;
    const int warp = tid >> 5;
    const int lane = tid & 31;
    const int wm   = warp >> 1;
    const int wn   = warp & 1;
    const int row0 = blockIdx.x * 128;
    const int col0 = blockIdx.y * 128;

    float acc[2][8][4];
#pragma unroll
    for (int mt = 0; mt < 2; mt++)
#pragma unroll
        for (int nt = 0; nt < 8; nt++)
#pragma unroll
            for (int q = 0; q < 4; q++) acc[mt][nt][q] = 0.f;

    const int aRow = wm * 32 + (lane & 15);
    const int aColOff = ((lane >> 4) & 1) * 8;
    const int bRowBase = wn * 64 + (lane & 7) + (((lane >> 4) & 1) << 3);
    const int bColOff  = ((lane >> 3) & 1) * 8;

    const int r  = tid >> 1;       // 0..127
    const int hf = tid & 1;        // half: 16 bf16 each

    const int NC = K >> 5;
    for (int c = 0; c < NC; c++) {
        const int k0g = c << 5;
        // A chunk [128 x 32] bf16 hi/lo: 2x16B per buffer per thread
        {
            bool ok = (row0 + r) < M;
            size_t go = (size_t)(row0 + r) * K + k0g + hf * 16;
            uint4 z = make_uint4(0,0,0,0);
            uint4 vh0 = ok ? *(const uint4*)(Ah + go)     : z;
            uint4 vh1 = ok ? *(const uint4*)(Ah + go + 8) : z;
            uint4 vl0 = ok ? *(const uint4*)(Al + go)     : z;
            uint4 vl1 = ok ? *(const uint4*)(Al + go + 8) : z;
            __nv_bfloat16* dh = sAh + r * SPITCH + hf * 16;
            __nv_bfloat16* dl = sAl + r * SPITCH + hf * 16;
            *(uint4*)dh = vh0; *(uint4*)(dh + 8) = vh1;
            *(uint4*)dl = vl0; *(uint4*)(dl + 8) = vl1;
        }
        // B chunk [128 n x 32 k] from [N][K]: same pattern
        {
            size_t go = (size_t)(col0 + r) * K + k0g + hf * 16;
            uint4 vh0 = *(const uint4*)(Bh + go);
            uint4 vh1 = *(const uint4*)(Bh + go + 8);
            uint4 vl0 = *(const uint4*)(Bl + go);
            uint4 vl1 = *(const uint4*)(Bl + go + 8);
            __nv_bfloat16* dh = sBh + r * SPITCH + hf * 16;
            __nv_bfloat16* dl = sBl + r * SPITCH + hf * 16;
            *(uint4*)dh = vh0; *(uint4*)(dh + 8) = vh1;
            *(uint4*)dl = vl0; *(uint4*)(dl + 8) = vl1;
        }
        __syncthreads();

#pragma unroll
        for (int ks = 0; ks < 2; ks++) {
            const int k0 = ks * 16;
            uint32_t ah[2][4], al[2][4];
#pragma unroll
            for (int mt = 0; mt < 2; mt++) {
                uint32_t offA = (uint32_t)(((aRow + mt * 16) * SPITCH + k0 + aColOff) * 2);
                ldmx4(ah[mt], smem_u32(sAh) + offA);
                ldmx4(al[mt], smem_u32(sAl) + offA);
            }
#pragma unroll
            for (int np = 0; np < 4; np++) {
                uint32_t bh[4], bl[4];
                uint32_t offB = (uint32_t)(((bRowBase + np * 16) * SPITCH + k0 + bColOff) * 2);
                ldmx4(bh, smem_u32(sBh) + offB);
                ldmx4(bl, smem_u32(sBl) + offB);
#pragma unroll
                for (int sub = 0; sub < 2; sub++) {
                    int nt = np * 2 + sub, od = sub * 2;
#pragma unroll
                    for (int mt = 0; mt < 2; mt++) {
                        mma16816(acc[mt][nt], ah[mt], bh[od], bh[od + 1]);
                        mma16816(acc[mt][nt], al[mt], bh[od], bh[od + 1]);
                        mma16816(acc[mt][nt], ah[mt], bl[od], bl[od + 1]);
                    }
                }
            }
        }
        __syncthreads();
    }

    // ---- epilogue ----
#pragma unroll
    for (int mt = 0; mt < 2; mt++) {
        int r0 = row0 + wm * 32 + mt * 16 + (lane >> 2);
#pragma unroll
        for (int nt = 0; nt < 8; nt++) {
            int cb = col0 + wn * 64 + nt * 8 + (lane & 3) * 2;
            float b0 = bias[cb], b1 = bias[cb + 1];
            float v0 = acc[mt][nt][0] + b0, v1 = acc[mt][nt][1] + b1;
            float v2 = acc[mt][nt][2] + b0, v3 = acc[mt][nt][3] + b1;
            if (ACT) {
                v0 = fmaxf(v0, 0.f); v1 = fmaxf(v1, 0.f);
                v2 = fmaxf(v2, 0.f); v3 = fmaxf(v3, 0.f);
            }
            if (OMODE == 0) {
                if (r0 < M)     *(float2*)&Cf[(size_t)r0 * Ncols + cb]       = make_float2(v0, v1);
                if (r0 + 8 < M) *(float2*)&Cf[(size_t)(r0 + 8) * Ncols + cb] = make_float2(v2, v3);
            } else {
                unsigned short h0,l0,h1,l1;
                if (r0 < M) {
                    split1(v0, h0, l0); split1(v1, h1, l1);
                    *(uint32_t*)&g_hidh[(size_t)r0 * Ncols + cb] = (uint32_t)h0 | ((uint32_t)h1 << 16);
                    *(uint32_t*)&g_hidl[(size_t)r0 * Ncols + cb] = (uint32_t)l0 | ((uint32_t)l1 << 16);
                }
                if (r0 + 8 < M) {
                    split1(v2, h0, l0); split1(v3, h1, l1);
                    *(uint32_t*)&g_hidh[(size_t)(r0 + 8) * Ncols + cb] = (uint32_t)h0 | ((uint32_t)h1 << 16);
                    *(uint32_t*)&g_hidl[(size_t)(r0 + 8) * Ncols + cb] = (uint32_t)l0 | ((uint32_t)l1 << 16);
                }
            }
        }
    }
}

// ---------------- fused GATv2 aggregation + residual + LN1 (one warp per node) ----------------
// writes fp32 h AND its bf16 hi/lo split (FFN1 A-operand)
__global__ void k_gat(const float* __restrict__ x, const float* __restrict__ att,
                      const float* __restrict__ bias_gat,
                      const float* __restrict__ g1, const float* __restrict__ be1) {
    int warp = (blockIdx.x * blockDim.x + threadIdx.x) >> 5;
    int lane = threadIdx.x & 31;
    if (warp >= TNq) return;
    const int i = warp;

    float4 xr = *(const float4*)&g_xr[(size_t)i * Dq + lane * 4];
    float4 at = *(const float4*)&att[lane * 4];

    float m = -1e30f, s = 0.f;
    float ax = 0.f, ay = 0.f, az = 0.f, aw = 0.f;

    int beg = g_rowptr[i], end = g_rowptr[i + 1];
    for (int e = beg; e < end; e++) {
        int j = clampi(g_esrc[e], 0, TNq - 1);
        float4 xl = *(const float4*)&g_xl[(size_t)j * Dq + lane * 4];
        float t0 = xl.x + xr.x; t0 = t0 > 0.f ? t0 : NEG * t0;
        float t1 = xl.y + xr.y; t1 = t1 > 0.f ? t1 : NEG * t1;
        float t2 = xl.z + xr.z; t2 = t2 > 0.f ? t2 : NEG * t2;
        float t3 = xl.w + xr.w; t3 = t3 > 0.f ? t3 : NEG * t3;
        float p = t0 * at.x + t1 * at.y + t2 * at.z + t3 * at.w;
        p += __shfl_xor_sync(0xffffffffu, p, 1);
        p += __shfl_xor_sync(0xffffffffu, p, 2);
        float nm = fmaxf(m, p);
        float sc = __expf(m - nm);
        float w  = __expf(p - nm);
        s  = s * sc + w;
        ax = ax * sc + w * xl.x;
        ay = ay * sc + w * xl.y;
        az = az * sc + w * xl.z;
        aw = aw * sc + w * xl.w;
        m = nm;
    }
    float inv = 1.f / s;

    float4 xv = *(const float4*)&x[(size_t)i * Dq + lane * 4];
    float4 bg = *(const float4*)&bias_gat[lane * 4];
    float o0 = ax * inv + bg.x + xv.x;
    float o1 = ay * inv + bg.y + xv.y;
    float o2 = az * inv + bg.z + xv.z;
    float o3 = aw * inv + bg.w + xv.w;

    float sum = o0 + o1 + o2 + o3;
    float sq  = o0*o0 + o1*o1 + o2*o2 + o3*o3;
#pragma unroll
    for (int off = 16; off > 0; off >>= 1) {
        sum += __shfl_xor_sync(0xffffffffu, sum, off);
        sq  += __shfl_xor_sync(0xffffffffu, sq, off);
    }
    float mu  = sum * (1.f / 128.f);
    float var = sq * (1.f / 128.f) - mu * mu;
    float rs  = rsqrtf(var + 1e-5f);
    float4 gv = *(const float4*)&g1[lane * 4];
    float4 bv = *(const float4*)&be1[lane * 4];
    float4 hres;
    hres.x = (o0 - mu) * rs * gv.x + bv.x;
    hres.y = (o1 - mu) * rs * gv.y + bv.y;
    hres.z = (o2 - mu) * rs * gv.z + bv.z;
    hres.w = (o3 - mu) * rs * gv.w + bv.w;
    size_t idx = (size_t)i * Dq + lane * 4;
    *(float4*)&g_h[idx] = hres;
    unsigned short h0,l0,h1,l1,h2,l2,h3,l3;
    split1(hres.x, h0, l0); split1(hres.y, h1, l1);
    split1(hres.z, h2, l2); split1(hres.w, h3, l3);
    *(uint2*)&g_hh[idx] = make_uint2((uint32_t)h0 | ((uint32_t)h1 << 16), (uint32_t)h2 | ((uint32_t)h3 << 16));
    *(uint2*)&g_hl[idx] = make_uint2((uint32_t)l0 | ((uint32_t)l1 << 16), (uint32_t)l2 | ((uint32_t)l3 << 16));
}

// ---------------- final residual + LN2 -> output ----------------
__global__ void k_ln2(const float* __restrict__ g2, const float* __restrict__ be2,
                      float* __restrict__ out) {
    int warp = (blockIdx.x * blockDim.x + threadIdx.x) >> 5;
    int lane = threadIdx.x & 31;
    if (warp >= TNq) return;
    const int i = warp;
    float4 h4 = *(const float4*)&g_h   [(size_t)i * Dq + lane * 4];
    float4 t4 = *(const float4*)&g_tmp2[(size_t)i * Dq + lane * 4];
    float o0 = h4.x + t4.x;
    float o1 = h4.y + t4.y;
    float o2 = h4.z + t4.z;
    float o3 = h4.w + t4.w;
    float sum = o0 + o1 + o2 + o3;
    float sq  = o0*o0 + o1*o1 + o2*o2 + o3*o3;
#pragma unroll
    for (int off = 16; off > 0; off >>= 1) {
        sum += __shfl_xor_sync(0xffffffffu, sum, off);
        sq  += __shfl_xor_sync(0xffffffffu, sq, off);
    }
    float mu  = sum * (1.f / 128.f);
    float var = sq * (1.f / 128.f) - mu * mu;
    float rs  = rsqrtf(var + 1e-5f);
    float4 gv = *(const float4*)&g2[lane * 4];
    float4 bv = *(const float4*)&be2[lane * 4];
    float4 o;
    o.x = (o0 - mu) * rs * gv.x + bv.x;
    o.y = (o1 - mu) * rs * gv.y + bv.y;
    o.z = (o2 - mu) * rs * gv.z + bv.z;
    o.w = (o3 - mu) * rs * gv.w + bv.w;
    *(float4*)&out[(size_t)i * Dq + lane * 4] = o;
}

// ---------------- launch ----------------
extern "C" void kernel_launch(void* const* d_in, const int* in_sizes, int n_in,
                              void* d_out, int out_size) {
    const float* x        = (const float*)d_in[0];
    const int*   ew       = (const int*)d_in[1];
    const float* Wl       = (const float*)d_in[2];
    const float* bl       = (const float*)d_in[3];
    const float* Wr       = (const float*)d_in[4];
    const float* br       = (const float*)d_in[5];
    const float* att      = (const float*)d_in[6];
    const float* bias_gat = (const float*)d_in[7];
    const float* W1       = (const float*)d_in[8];
    const float* b1       = (const float*)d_in[9];
    const float* W2       = (const float*)d_in[10];
    const float* b2       = (const float*)d_in[11];
    const float* g1       = (const float*)d_in[12];
    const float* be1      = (const float*)d_in[13];
    const float* g2       = (const float*)d_in[14];
    const float* be2      = (const float*)d_in[15];
    float*       out      = (float*)d_out;

    // dtype detection + CSR build + operand prep
    k_detect<<<1, 1024>>>(ew);
    k_zero_counts<<<(TNq + 255) / 256, 256>>>();
    k_count<<<(ETOT + 255) / 256, 256>>>(ew);
    k_scan1<<<SCANB, 1024>>>();
    k_scan2<<<1, 128>>>();
    k_scan3<<<SCANB, 1024>>>();
    k_scatter<<<(ETOT + 255) / 256, 256>>>(ew);
    k_prep_w<<<(WT_TOT + 255) / 256, 256>>>(Wl, Wr, W1, W2);
    k_split_x<<<(TNq * (Dq / 4) + 255) / 256, 256>>>(x);

    const int MT = (TNq + 127) / 128;   // 663

    // x_l / x_r projections
    k_tgemm<0, ASRC_X, 0, COUT_XL><<<dim3(MT, 1), 256>>>(bl, TNq, Dq, Dq, 0, 0);
    k_tgemm<0, ASRC_X, 0, COUT_XR><<<dim3(MT, 1), 256>>>(br, TNq, Dq, Dq, 0, 0);

    // fused GATv2 softmax-aggregate + residual + LN1 -> g_h (+ bf16 split)
    k_gat<<<(TNq * 32 + 255) / 256, 256>>>(x, att, bias_gat, g1, be1);

    // FFN, sliced over M (hidden kept only as bf16 hi/lo)
    const int MTS = (SLQ + 127) / 128;  // 332
    for (int s = 0; s < NSLICE; s++) {
        int r0 = s * SLQ;
        k_tgemm<1, ASRC_H,   1, COUT_TMP2><<<dim3(MTS, FFq / 128), 256>>>(b1, SLQ, FFq, Dq,  r0, 0);
        k_tgemm<0, ASRC_HID, 0, COUT_TMP2><<<dim3(MTS, Dq  / 128), 256>>>(b2, SLQ, Dq,  FFq, 0,  r0);
    }

    // residual + LN2 -> out
    k_ln2<<<(TNq * 32 + 255) / 256, 256>>>(g2, be2, out);
}

// round 16
// speedup vs baseline: 2.5099x; 1.1472x over previous
#include <cuda_runtime.h>
#include <cuda_bf16.h>
#include <cstdint>

// ---------------- problem constants ----------------
#define Bq   8
#define Tq   12
#define Nq   883
#define Dq   128
#define Eq   7000
#define FFq  2048
#define BTq  (Bq*Tq)            // 96
#define TNq  (BTq*Nq)           // 84768
#define EEq  (BTq*Eq)           // 672000
#define ETOT (EEq+TNq)          // 756768
#define NEG  0.2f

#define NSLICE 2
#define SLQ    (TNq / NSLICE)   // 42384

// weight-transpose buffer offsets ([N][K] bf16 hi/lo)
#define OFF_WL 0
#define OFF_WR (128*128)
#define OFF_W1 (2*128*128)
#define OFF_W2 (OFF_W1 + 2048*128)
#define WT_TOT (OFF_W2 + 128*2048)

// ---------------- scratch (device globals; no allocations allowed) ----------------
__device__ float g_xl[(size_t)TNq*Dq];
__device__ float g_xr[(size_t)TNq*Dq];
__device__ float g_h [(size_t)TNq*Dq];
__device__ float g_tmp2[(size_t)TNq*Dq];
__device__ __nv_bfloat16 g_xh [(size_t)TNq*Dq];
__device__ __nv_bfloat16 g_xlo[(size_t)TNq*Dq];
__device__ __nv_bfloat16 g_hh [(size_t)TNq*Dq];
__device__ __nv_bfloat16 g_hl [(size_t)TNq*Dq];
__device__ __nv_bfloat16 g_hidh[(size_t)SLQ*FFq];
__device__ __nv_bfloat16 g_hidl[(size_t)SLQ*FFq];
__device__ __nv_bfloat16 g_wth[WT_TOT];
__device__ __nv_bfloat16 g_wtl[WT_TOT];
__device__ int   g_count[TNq];
__device__ int   g_rowptr[TNq+1];
__device__ int   g_cursor[TNq];
__device__ int   g_esrc[ETOT];
__device__ int   g_is64;
__device__ int   g_bsum[128];

__device__ __forceinline__ int clampi(int v, int lo, int hi) {
    return v < lo ? lo : (v > hi ? hi : v);
}
__device__ __forceinline__ uint32_t smem_u32(const void* p) {
    uint32_t a;
    asm("{ .reg .u64 t; cvta.to.shared.u64 t, %1; cvt.u32.u64 %0, t; }" : "=r"(a) : "l"(p));
    return a;
}
__device__ __forceinline__ void split1(float a, unsigned short& h, unsigned short& l) {
    __nv_bfloat16 ha = __float2bfloat16(a);
    h = __bfloat16_as_ushort(ha);
    l = __bfloat16_as_ushort(__float2bfloat16(a - __bfloat162float(ha)));
}
__device__ __forceinline__ void ldmx4(uint32_t* r, uint32_t addr) {
    asm volatile("ldmatrix.sync.aligned.m8n8.x4.shared.b16 {%0,%1,%2,%3}, [%4];"
                 : "=r"(r[0]), "=r"(r[1]), "=r"(r[2]), "=r"(r[3]) : "r"(addr));
}
__device__ __forceinline__ void mma16816(float* c, const uint32_t* a, uint32_t b0, uint32_t b1) {
    asm volatile(
        "mma.sync.aligned.m16n8k16.row.col.f32.bf16.bf16.f32 "
        "{%0,%1,%2,%3}, {%4,%5,%6,%7}, {%8,%9}, {%0,%1,%2,%3};"
        : "+f"(c[0]), "+f"(c[1]), "+f"(c[2]), "+f"(c[3])
        : "r"(a[0]), "r"(a[1]), "r"(a[2]), "r"(a[3]), "r"(b0), "r"(b1));
}
__device__ __forceinline__ void cpa16(uint32_t smem, const void* g, int src_sz) {
    asm volatile("cp.async.cg.shared.global [%0], [%1], 16, %2;"
                 :: "r"(smem), "l"(g), "r"(src_sz));
}
__device__ __forceinline__ void cpa_commit() {
    asm volatile("cp.async.commit_group;");
}
template<int N>
__device__ __forceinline__ void cpa_wait() {
    asm volatile("cp.async.wait_group %0;" :: "n"(N));
}

// ---------------- edge_index dtype detection ----------------
__global__ void k_detect(const int* __restrict__ w) {
    __shared__ int any;
    if (threadIdx.x == 0) any = 0;
    __syncthreads();
    int local = 0;
    for (int k = 1 + 2 * (int)threadIdx.x; k < 2 * Eq; k += 2 * (int)blockDim.x)
        local |= w[k];
    if (local) atomicOr(&any, 1);
    __syncthreads();
    if (threadIdx.x == 0) g_is64 = (any == 0) ? 1 : 0;
}
__device__ __forceinline__ int edge_src(const int* w, int k, int is64) {
    int v = is64 ? w[2 * k] : w[k];
    return clampi(v, 0, Nq - 1);
}
__device__ __forceinline__ int edge_dst(const int* w, int k, int is64) {
    int v = is64 ? w[2 * (Eq + k)] : w[Eq + k];
    return clampi(v, 0, Nq - 1);
}

// ---------------- CSR construction ----------------
__global__ void k_zero_counts() {
    int i = blockIdx.x*blockDim.x + threadIdx.x;
    if (i < TNq) g_count[i] = 0;
}
__global__ void k_count(const int* __restrict__ ew) {
    int e = blockIdx.x*blockDim.x + threadIdx.x;
    if (e >= ETOT) return;
    const int is64 = g_is64;
    int dst;
    if (e < EEq) {
        int b = e / Eq;
        int k = e - b*Eq;
        dst = edge_dst(ew, k, is64) + b*Nq;
    } else {
        dst = e - EEq;
    }
    atomicAdd(&g_count[dst], 1);
}

#define SCANB ((TNq + 1023) / 1024)   // 83
__global__ void k_scan1() {
    __shared__ int red[1024];
    int t = threadIdx.x;
    int idx = blockIdx.x * 1024 + t;
    int v = (idx < TNq) ? g_count[idx] : 0;
    red[t] = v;
    __syncthreads();
    for (int off = 512; off > 0; off >>= 1) {
        if (t < off) red[t] += red[t + off];
        __syncthreads();
    }
    if (t == 0) g_bsum[blockIdx.x] = red[0];
}
__global__ void k_scan2() {
    __shared__ int s[128];
    int t = threadIdx.x;
    int v = (t < SCANB) ? g_bsum[t] : 0;
    s[t] = v;
    __syncthreads();
    for (int off = 1; off < 128; off <<= 1) {
        int u = (t >= off) ? s[t - off] : 0;
        __syncthreads();
        s[t] += u;
        __syncthreads();
    }
    if (t < SCANB) g_bsum[t] = s[t] - v;
}
__global__ void k_scan3() {
    __shared__ int s[1024];
    int t = threadIdx.x;
    int idx = blockIdx.x * 1024 + t;
    int v = (idx < TNq) ? g_count[idx] : 0;
    s[t] = v;
    __syncthreads();
    for (int off = 1; off < 1024; off <<= 1) {
        int u = (t >= off) ? s[t - off] : 0;
        __syncthreads();
        s[t] += u;
        __syncthreads();
    }
    int ex = g_bsum[blockIdx.x] + s[t] - v;
    if (idx < TNq) { g_rowptr[idx] = ex; g_cursor[idx] = ex; }
    if (blockIdx.x == 0 && t == 0) g_rowptr[TNq] = ETOT;
}

__global__ void k_scatter(const int* __restrict__ ew) {
    int e = blockIdx.x*blockDim.x + threadIdx.x;
    if (e >= ETOT) return;
    const int is64 = g_is64;
    int src, dst;
    if (e < EEq) {
        int b = e / Eq;
        int k = e - b*Eq;
        src = edge_src(ew, k, is64) + b*Nq;
        dst = edge_dst(ew, k, is64) + b*Nq;
    } else {
        src = dst = e - EEq;
    }
    int pos = atomicAdd(&g_cursor[dst], 1);
    pos = clampi(pos, 0, ETOT - 1);
    g_esrc[pos] = src;
}

// ---------------- weight transpose + split ----------------
__global__ void k_prep_w(const float* __restrict__ Wl, const float* __restrict__ Wr,
                         const float* __restrict__ W1, const float* __restrict__ W2) {
    int idx = blockIdx.x * blockDim.x + threadIdx.x;
    if (idx >= WT_TOT) return;
    float v;
    if (idx < OFF_WR) {
        int q = idx - OFF_WL, n = q >> 7, k = q & 127;
        v = Wl[k * 128 + n];
    } else if (idx < OFF_W1) {
        int q = idx - OFF_WR, n = q >> 7, k = q & 127;
        v = Wr[k * 128 + n];
    } else if (idx < OFF_W2) {
        int q = idx - OFF_W1, n = q >> 7, k = q & 127;
        v = W1[k * 2048 + n];
    } else {
        int q = idx - OFF_W2, n = q >> 11, k = q & 2047;
        v = W2[k * 128 + n];
    }
    unsigned short h, l;
    split1(v, h, l);
    g_wth[idx] = __ushort_as_bfloat16(h);
    g_wtl[idx] = __ushort_as_bfloat16(l);
}

// ---------------- split x into bf16 hi/lo ----------------
__global__ void k_split_x(const float* __restrict__ x) {
    size_t i = (size_t)(blockIdx.x * blockDim.x + threadIdx.x) * 4;
    if (i >= (size_t)TNq * Dq) return;
    float4 v = *(const float4*)&x[i];
    unsigned short h0,l0,h1,l1,h2,l2,h3,l3;
    split1(v.x, h0, l0); split1(v.y, h1, l1);
    split1(v.z, h2, l2); split1(v.w, h3, l3);
    *(uint2*)&g_xh[i]  = make_uint2((uint32_t)h0 | ((uint32_t)h1 << 16), (uint32_t)h2 | ((uint32_t)h3 << 16));
    *(uint2*)&g_xlo[i] = make_uint2((uint32_t)l0 | ((uint32_t)l1 << 16), (uint32_t)l2 | ((uint32_t)l3 << 16));
}

// ---------------- HMMA GEMM, cp.async double-buffered pipeline ----------------
// K-chunk 16, 2 smem stages (48KB total). Tile 128x128, 8 warps = 4(M) x 2(N).
#define SP2 24    // bf16 elems/row = 48B: 16B-aligned rows, 12-bank stride (conflict-free)
#define STAGE_E (128 * SP2)
#define ASRC_X   0
#define ASRC_H   1
#define ASRC_HID 2
#define COUT_XL   0
#define COUT_XR   1
#define COUT_TMP2 2
template<int ACT, int AID, int OMODE, int CID>
__global__ void __launch_bounds__(256, 2)
k_tgemm(const float* __restrict__ bias, int M, int Ncols, int K, int a_off, int c_off) {
    const __nv_bfloat16* Ah;
    const __nv_bfloat16* Al;
    if (AID == ASRC_X)      { Ah = g_xh;   Al = g_xlo; }
    else if (AID == ASRC_H) { Ah = g_hh;   Al = g_hl; }
    else                    { Ah = g_hidh; Al = g_hidl; }
    Ah += (size_t)a_off * K;
    Al += (size_t)a_off * K;
    int wt_off = (AID == ASRC_X) ? (CID == COUT_XL ? OFF_WL : OFF_WR)
               : (AID == ASRC_H) ? OFF_W1 : OFF_W2;
    const __nv_bfloat16* __restrict__ Bh = g_wth + wt_off;
    const __nv_bfloat16* __restrict__ Bl = g_wtl + wt_off;
    float* Cf = (CID == COUT_XL) ? g_xl : (CID == COUT_XR) ? g_xr : g_tmp2;
    Cf += (size_t)c_off * Ncols;

    __shared__ __align__(16) __nv_bfloat16 sAh[2 * STAGE_E];
    __shared__ __align__(16) __nv_bfloat16 sAl[2 * STAGE_E];
    __shared__ __align__(16) __nv_bfloat16 sBh[2 * STAGE_E];
    __shared__ __align__(16) __nv_bfloat16 sBl[2 * STAGE_E];

    const int tid  = threadIdx.x;
    const int warp = tid >> 5;
    const int lane = tid & 31;
    const int wm   = warp >> 1;
    const int wn   = warp & 1;
    const int row0 = blockIdx.x * 128;
    const int col0 = blockIdx.y * 128;

    float acc[2][8][4];
#pragma unroll
    for (int mt = 0; mt < 2; mt++)
#pragma unroll
        for (int nt = 0; nt < 8; nt++)
#pragma unroll
            for (int q = 0; q < 4; q++) acc[mt][nt][q] = 0.f;

    const int aRow = wm * 32 + (lane & 15);
    const int aColOff = ((lane >> 4) & 1) * 8;
    const int bRowBase = wn * 64 + (lane & 7) + (((lane >> 4) & 1) << 3);
    const int bColOff  = ((lane >> 3) & 1) * 8;

    const int r  = tid >> 1;        // 0..127
    const int hf = tid & 1;         // 8-element half of 16-wide chunk
    const int aOK = ((row0 + r) < M) ? 16 : 0;
    const int ar  = clampi(row0 + r, 0, M - 1);   // in-bounds address even when zfilled

    const uint32_t bAh = smem_u32(sAh), bAl = smem_u32(sAl);
    const uint32_t bBh = smem_u32(sBh), bBl = smem_u32(sBl);
    const uint32_t sOff = (uint32_t)((r * SP2 + hf * 8) * 2);

    const int NC = K >> 4;

    // prologue: prefetch chunk 0 into stage 0
    {
        size_t goA = (size_t)ar * K + hf * 8;
        size_t goB = (size_t)(col0 + r) * K + hf * 8;
        cpa16(bAh + sOff, Ah + goA, aOK);
        cpa16(bAl + sOff, Al + goA, aOK);
        cpa16(bBh + sOff, Bh + goB, 16);
        cpa16(bBl + sOff, Bl + goB, 16);
        cpa_commit();
    }

    for (int c = 0; c < NC; c++) {
        const uint32_t stB = (uint32_t)((c & 1) * STAGE_E * 2);   // byte offset of current stage
        if (c + 1 < NC) {
            const uint32_t nB = (uint32_t)(((c + 1) & 1) * STAGE_E * 2);
            const int k0g = (c + 1) << 4;
            size_t goA = (size_t)ar * K + k0g + hf * 8;
            size_t goB = (size_t)(col0 + r) * K + k0g + hf * 8;
            cpa16(bAh + nB + sOff, Ah + goA, aOK);
            cpa16(bAl + nB + sOff, Al + goA, aOK);
            cpa16(bBh + nB + sOff, Bh + goB, 16);
            cpa16(bBl + nB + sOff, Bl + goB, 16);
            cpa_commit();
            cpa_wait<1>();
        } else {
            cpa_wait<0>();
        }
        __syncthreads();

        // one k-step of 16
        uint32_t ah[2][4], al[2][4];
#pragma unroll
        for (int mt = 0; mt < 2; mt++) {
            uint32_t offA = stB + (uint32_t)(((aRow + mt * 16) * SP2 + aColOff) * 2);
            ldmx4(ah[mt], bAh + offA);
            ldmx4(al[mt], bAl + offA);
        }
#pragma unroll
        for (int np = 0; np < 4; np++) {
            uint32_t bh[4], bl[4];
            uint32_t offB = stB + (uint32_t)(((bRowBase + np * 16) * SP2 + bColOff) * 2);
            ldmx4(bh, bBh + offB);
            ldmx4(bl, bBl + offB);
#pragma unroll
            for (int sub = 0; sub < 2; sub++) {
                int nt = np * 2 + sub, od = sub * 2;
#pragma unroll
                for (int mt = 0; mt < 2; mt++) {
                    mma16816(acc[mt][nt], ah[mt], bh[od], bh[od + 1]);
                    mma16816(acc[mt][nt], al[mt], bh[od], bh[od + 1]);
                    mma16816(acc[mt][nt], ah[mt], bl[od], bl[od + 1]);
                }
            }
        }
        __syncthreads();
    }

    // ---- epilogue ----
#pragma unroll
    for (int mt = 0; mt < 2; mt++) {
        int r0 = row0 + wm * 32 + mt * 16 + (lane >> 2);
#pragma unroll
        for (int nt = 0; nt < 8; nt++) {
            int cb = col0 + wn * 64 + nt * 8 + (lane & 3) * 2;
            float b0 = bias[cb], b1 = bias[cb + 1];
            float v0 = acc[mt][nt][0] + b0, v1 = acc[mt][nt][1] + b1;
            float v2 = acc[mt][nt][2] + b0, v3 = acc[mt][nt][3] + b1;
            if (ACT) {
                v0 = fmaxf(v0, 0.f); v1 = fmaxf(v1, 0.f);
                v2 = fmaxf(v2, 0.f); v3 = fmaxf(v3, 0.f);
            }
            if (OMODE == 0) {
                if (r0 < M)     *(float2*)&Cf[(size_t)r0 * Ncols + cb]       = make_float2(v0, v1);
                if (r0 + 8 < M) *(float2*)&Cf[(size_t)(r0 + 8) * Ncols + cb] = make_float2(v2, v3);
            } else {
                unsigned short h0,l0,h1,l1;
                if (r0 < M) {
                    split1(v0, h0, l0); split1(v1, h1, l1);
                    *(uint32_t*)&g_hidh[(size_t)r0 * Ncols + cb] = (uint32_t)h0 | ((uint32_t)h1 << 16);
                    *(uint32_t*)&g_hidl[(size_t)r0 * Ncols + cb] = (uint32_t)l0 | ((uint32_t)l1 << 16);
                }
                if (r0 + 8 < M) {
                    split1(v2, h0, l0); split1(v3, h1, l1);
                    *(uint32_t*)&g_hidh[(size_t)(r0 + 8) * Ncols + cb] = (uint32_t)h0 | ((uint32_t)h1 << 16);
                    *(uint32_t*)&g_hidl[(size_t)(r0 + 8) * Ncols + cb] = (uint32_t)l0 | ((uint32_t)l1 << 16);
                }
            }
        }
    }
}

// ---------------- fused GATv2 aggregation + residual + LN1 ----------------
__global__ void k_gat(const float* __restrict__ x, const float* __restrict__ att,
                      const float* __restrict__ bias_gat,
                      const float* __restrict__ g1, const float* __restrict__ be1) {
    int warp = (blockIdx.x * blockDim.x + threadIdx.x) >> 5;
    int lane = threadIdx.x & 31;
    if (warp >= TNq) return;
    const int i = warp;

    float4 xr = *(const float4*)&g_xr[(size_t)i * Dq + lane * 4];
    float4 at = *(const float4*)&att[lane * 4];

    float m = -1e30f, s = 0.f;
    float ax = 0.f, ay = 0.f, az = 0.f, aw = 0.f;

    int beg = g_rowptr[i], end = g_rowptr[i + 1];
    for (int e = beg; e < end; e++) {
        int j = clampi(g_esrc[e], 0, TNq - 1);
        float4 xl = *(const float4*)&g_xl[(size_t)j * Dq + lane * 4];
        float t0 = xl.x + xr.x; t0 = t0 > 0.f ? t0 : NEG * t0;
        float t1 = xl.y + xr.y; t1 = t1 > 0.f ? t1 : NEG * t1;
        float t2 = xl.z + xr.z; t2 = t2 > 0.f ? t2 : NEG * t2;
        float t3 = xl.w + xr.w; t3 = t3 > 0.f ? t3 : NEG * t3;
        float p = t0 * at.x + t1 * at.y + t2 * at.z + t3 * at.w;
        p += __shfl_xor_sync(0xffffffffu, p, 1);
        p += __shfl_xor_sync(0xffffffffu, p, 2);
        float nm = fmaxf(m, p);
        float sc = __expf(m - nm);
        float w  = __expf(p - nm);
        s  = s * sc + w;
        ax = ax * sc + w * xl.x;
        ay = ay * sc + w * xl.y;
        az = az * sc + w * xl.z;
        aw = aw * sc + w * xl.w;
        m = nm;
    }
    float inv = 1.f / s;

    float4 xv = *(const float4*)&x[(size_t)i * Dq + lane * 4];
    float4 bg = *(const float4*)&bias_gat[lane * 4];
    float o0 = ax * inv + bg.x + xv.x;
    float o1 = ay * inv + bg.y + xv.y;
    float o2 = az * inv + bg.z + xv.z;
    float o3 = aw * inv + bg.w + xv.w;

    float sum = o0 + o1 + o2 + o3;
    float sq  = o0*o0 + o1*o1 + o2*o2 + o3*o3;
#pragma unroll
    for (int off = 16; off > 0; off >>= 1) {
        sum += __shfl_xor_sync(0xffffffffu, sum, off);
        sq  += __shfl_xor_sync(0xffffffffu, sq, off);
    }
    float mu  = sum * (1.f / 128.f);
    float var = sq * (1.f / 128.f) - mu * mu;
    float rs  = rsqrtf(var + 1e-5f);
    float4 gv = *(const float4*)&g1[lane * 4];
    float4 bv = *(const float4*)&be1[lane * 4];
    float4 hres;
    hres.x = (o0 - mu) * rs * gv.x + bv.x;
    hres.y = (o1 - mu) * rs * gv.y + bv.y;
    hres.z = (o2 - mu) * rs * gv.z + bv.z;
    hres.w = (o3 - mu) * rs * gv.w + bv.w;
    size_t idx = (size_t)i * Dq + lane * 4;
    *(float4*)&g_h[idx] = hres;
    unsigned short h0,l0,h1,l1,h2,l2,h3,l3;
    split1(hres.x, h0, l0); split1(hres.y, h1, l1);
    split1(hres.z, h2, l2); split1(hres.w, h3, l3);
    *(uint2*)&g_hh[idx] = make_uint2((uint32_t)h0 | ((uint32_t)h1 << 16), (uint32_t)h2 | ((uint32_t)h3 << 16));
    *(uint2*)&g_hl[idx] = make_uint2((uint32_t)l0 | ((uint32_t)l1 << 16), (uint32_t)l2 | ((uint32_t)l3 << 16));
}

// ---------------- final residual + LN2 -> output ----------------
__global__ void k_ln2(const float* __restrict__ g2, const float* __restrict__ be2,
                      float* __restrict__ out) {
    int warp = (blockIdx.x * blockDim.x + threadIdx.x) >> 5;
    int lane = threadIdx.x & 31;
    if (warp >= TNq) return;
    const int i = warp;
    float4 h4 = *(const float4*)&g_h   [(size_t)i * Dq + lane * 4];
    float4 t4 = *(const float4*)&g_tmp2[(size_t)i * Dq + lane * 4];
    float o0 = h4.x + t4.x;
    float o1 = h4.y + t4.y;
    float o2 = h4.z + t4.z;
    float o3 = h4.w + t4.w;
    float sum = o0 + o1 + o2 + o3;
    float sq  = o0*o0 + o1*o1 + o2*o2 + o3*o3;
#pragma unroll
    for (int off = 16; off > 0; off >>= 1) {
        sum += __shfl_xor_sync(0xffffffffu, sum, off);
        sq  += __shfl_xor_sync(0xffffffffu, sq, off);
    }
    float mu  = sum * (1.f / 128.f);
    float var = sq * (1.f / 128.f) - mu * mu;
    float rs  = rsqrtf(var + 1e-5f);
    float4 gv = *(const float4*)&g2[lane * 4];
    float4 bv = *(const float4*)&be2[lane * 4];
    float4 o;
    o.x = (o0 - mu) * rs * gv.x + bv.x;
    o.y = (o1 - mu) * rs * gv.y + bv.y;
    o.z = (o2 - mu) * rs * gv.z + bv.z;
    o.w = (o3 - mu) * rs * gv.w + bv.w;
    *(float4*)&out[(size_t)i * Dq + lane * 4] = o;
}

// ---------------- launch ----------------
extern "C" void kernel_launch(void* const* d_in, const int* in_sizes, int n_in,
                              void* d_out, int out_size) {
    const float* x        = (const float*)d_in[0];
    const int*   ew       = (const int*)d_in[1];
    const float* Wl       = (const float*)d_in[2];
    const float* bl       = (const float*)d_in[3];
    const float* Wr       = (const float*)d_in[4];
    const float* br       = (const float*)d_in[5];
    const float* att      = (const float*)d_in[6];
    const float* bias_gat = (const float*)d_in[7];
    const float* W1       = (const float*)d_in[8];
    const float* b1       = (const float*)d_in[9];
    const float* W2       = (const float*)d_in[10];
    const float* b2       = (const float*)d_in[11];
    const float* g1       = (const float*)d_in[12];
    const float* be1      = (const float*)d_in[13];
    const float* g2       = (const float*)d_in[14];
    const float* be2      = (const float*)d_in[15];
    float*       out      = (float*)d_out;

    // dtype detection + CSR build + operand prep
    k_detect<<<1, 1024>>>(ew);
    k_zero_counts<<<(TNq + 255) / 256, 256>>>();
    k_count<<<(ETOT + 255) / 256, 256>>>(ew);
    k_scan1<<<SCANB, 1024>>>();
    k_scan2<<<1, 128>>>();
    k_scan3<<<SCANB, 1024>>>();
    k_scatter<<<(ETOT + 255) / 256, 256>>>(ew);
    k_prep_w<<<(WT_TOT + 255) / 256, 256>>>(Wl, Wr, W1, W2);
    k_split_x<<<(TNq * (Dq / 4) + 255) / 256, 256>>>(x);

    const int MT = (TNq + 127) / 128;   // 663

    // x_l / x_r projections
    k_tgemm<0, ASRC_X, 0, COUT_XL><<<dim3(MT, 1), 256>>>(bl, TNq, Dq, Dq, 0, 0);
    k_tgemm<0, ASRC_X, 0, COUT_XR><<<dim3(MT, 1), 256>>>(br, TNq, Dq, Dq, 0, 0);

    // fused GATv2 softmax-aggregate + residual + LN1 -> g_h (+ bf16 split)
    k_gat<<<(TNq * 32 + 255) / 256, 256>>>(x, att, bias_gat, g1, be1);

    // FFN, sliced over M (hidden kept only as bf16 hi/lo)
    const int MTS = (SLQ + 127) / 128;  // 332
    for (int s = 0; s < NSLICE; s++) {
        int r0 = s * SLQ;
        k_tgemm<1, ASRC_H,   1, COUT_TMP2><<<dim3(MTS, FFq / 128), 256>>>(b1, SLQ, FFq, Dq,  r0, 0);
        k_tgemm<0, ASRC_HID, 0, COUT_TMP2><<<dim3(MTS, Dq  / 128), 256>>>(b2, SLQ, Dq,  FFq, 0,  r0);
    }

    // residual + LN2 -> out
    k_ln2<<<(TNq * 32 + 255) / 256, 256>>>(g2, be2, out);
}